// round 16
// baseline (speedup 1.0000x reference)
#include <cuda_runtime.h>
#include <math.h>

#define BB 64
#define NN 8732
#define CC 81
#define TN 64                       // anchors per conf tile
#define TPR ((NN + TN - 1) / TN)    // 137 tiles per row
#define NT (BB * TPR)               // 8768 tiles
#define NU4 (NN / 4)                // 2183 uint4 per key row

#define KEYS_BYTES 34944            // NN*4 = 34928, padded to 16
#define NBINS 16384
#define SEL_SMEM (KEYS_BYTES + NBINS * 4)   // 100480 B dynamic smem

// Scratch (device globals — no runtime allocation). Every word read is written
// first in the same launch sequence: deterministic, no init kernel.
__device__ unsigned g_keys[BB * NN];     // pos -> 0, else float bits of conf_loss
__device__ unsigned char g_cnt[NT];      // per-tile positive count
__device__ float g_psum[NT];             // per-tile sum of positive conf_loss
__device__ float g_locpart[NT];          // per-tile loc loss partial

// One 64-anchor tile per 256-thread block (EXACT R14 structure — proven
// fastest at 79.1us). Sole change: all single-use input streams are loaded
// with __ldcs (evict-first) so the 380MB of streaming data doesn't evict the
// ~2.3MB of inter-kernel scratch (g_keys/g_psum/...) from L2.
__global__ __launch_bounds__(256) void conf_kernel(const float* __restrict__ pc,
                                                   const float* __restrict__ gc,
                                                   const float* __restrict__ pl,
                                                   const float* __restrict__ gl) {
    __shared__ float sx[TN * CC];            // 20736 B raw pred_conf tile
    __shared__ float s_dot[TN];              // x[label] per anchor
    __shared__ unsigned char s_posb[TN];     // 1 if label != 0
    __shared__ float s_half[TN];             // Σexp classes [40,81)
    __shared__ float s_ps2[2];
    __shared__ int s_pc2[2];
    __shared__ float s_loc2[2];

    const int tid = threadIdx.x;
    const int lane = tid & 31;
    const int warp = tid >> 5;
    const int tile = blockIdx.x;
    const int b = blockIdx.y;
    const int n0 = tile * TN;
    const int nA = (n0 + TN <= NN) ? TN : (NN - n0);   // 64 or 28 (both %4==0)
    const int n4 = (nA * CC) >> 2;

    // hoisted loc loads (warps 4-5): issued before the staging loop, consumed
    // in phase 2 — latency rides under phase 1.
    float4 lA = make_float4(0.f, 0.f, 0.f, 0.f);
    float4 lG = make_float4(0.f, 0.f, 0.f, 0.f);
    if (tid >= 128 && tid < 192) {
        const int a = tid - 128;
        if (a < nA) {
            lA = __ldcs((const float4*)(pl + ((size_t)b * NN + n0) * 4) + a);
            lG = __ldcs((const float4*)(gl + ((size_t)b * NN + n0) * 4) + a);
        }
    }

    const size_t base = ((size_t)b * NN + n0) * CC;    // multiple of 4 floats
    const float4* p4 = (const float4*)(pc + base);
    const float4* g4 = (const float4*)(gc + base);
    for (int i = tid; i < n4; i += 256) {
        const float4 p = __ldcs(p4 + i);
        ((float4*)sx)[i] = p;
        const float4 g = __ldcs(g4 + i);
        if (g.x != 0.0f || g.y != 0.0f || g.z != 0.0f || g.w != 0.0f) {
            const float pv[4] = {p.x, p.y, p.z, p.w};
            const float gv[4] = {g.x, g.y, g.z, g.w};
            #pragma unroll
            for (int j = 0; j < 4; ++j) {
                if (gv[j] != 0.0f) {                   // gt one-hot: unique writer
                    const int f = 4 * i + j;
                    const int a = f / CC;
                    const int cls = f - a * CC;
                    s_dot[a] = pv[j] * gv[j];          // = x[label] (gt value 1.0)
                    s_posb[a] = (cls != 0) ? 1 : 0;
                }
            }
        }
    }
    __syncthreads();

    float myE = 0.0f;
    if (tid < 64) {
        // classes [0,40) for anchor tid; stride-81 rows -> conflict-free.
        if (tid < nA) {
            const float* x = sx + tid * CC;
            float e0 = 0.0f, e1 = 0.0f, e2 = 0.0f, e3 = 0.0f;
            #pragma unroll
            for (int c = 0; c < 40; c += 4) {
                e0 += __expf(x[c]);     e1 += __expf(x[c + 1]);
                e2 += __expf(x[c + 2]); e3 += __expf(x[c + 3]);
            }
            myE = (e0 + e1) + (e2 + e3);
        }
    } else if (tid < 128) {
        // classes [40,81) for anchor tid-64
        const int a = tid - 64;
        if (a < nA) {
            const float* x = sx + a * CC + 40;
            float e0 = 0.0f, e1 = 0.0f, e2 = 0.0f, e3 = 0.0f;
            #pragma unroll
            for (int c = 0; c < 40; c += 4) {
                e0 += __expf(x[c]);     e1 += __expf(x[c + 1]);
                e2 += __expf(x[c + 2]); e3 += __expf(x[c + 3]);
            }
            e0 += __expf(x[40]);                       // class 80
            s_half[a] = (e0 + e1) + (e2 + e3);
        }
    } else if (tid < 192) {
        // loc partial from the hoisted registers (no loads here).
        float ls = 0.0f;
        {
            float d, ad;
            d = lA.x - lG.x; ad = fabsf(d); if (ad > 1.0f) ls += ad - 0.5f;
            d = lA.y - lG.y; ad = fabsf(d); if (ad > 1.0f) ls += ad - 0.5f;
            d = lA.z - lG.z; ad = fabsf(d); if (ad > 1.0f) ls += ad - 0.5f;
            d = lA.w - lG.w; ad = fabsf(d); if (ad > 1.0f) ls += ad - 0.5f;
        }
        #pragma unroll
        for (int o = 16; o; o >>= 1) ls += __shfl_xor_sync(0xFFFFFFFFu, ls, o);
        if (lane == 0) s_loc2[warp - 4] = ls;
    }
    __syncthreads();

    if (tid < 64) {
        float pv = 0.0f;
        int pc_ = 0;
        if (tid < nA) {
            const float e = myE + s_half[tid];
            const float cl = __logf(e) - s_dot[tid];   // lse - x[label] > 0
            const bool pos = s_posb[tid];
            g_keys[b * NN + n0 + tid] = pos ? 0u : __float_as_uint(cl);
            if (pos) { pv = cl; pc_ = 1; }
        }
        #pragma unroll
        for (int o = 16; o; o >>= 1) {
            pv  += __shfl_xor_sync(0xFFFFFFFFu, pv, o);
            pc_ += __shfl_xor_sync(0xFFFFFFFFu, pc_, o);
        }
        if (lane == 0) { s_ps2[warp] = pv; s_pc2[warp] = pc_; }
    }
    __syncthreads();
    if (tid == 0) {
        const int t = b * TPR + tile;
        g_psum[t] = s_ps2[0] + s_ps2[1];
        g_cnt[t] = (unsigned char)(s_pc2[0] + s_pc2[1]);
        g_locpart[t] = s_loc2[0] + s_loc2[1];
    }
}

// One 1024-thread block per batch row. Adaptive-range rank-k select — EXACT
// R12/R14 state (proven 13.3us).
__global__ __launch_bounds__(1024) void select_kernel(float* __restrict__ out, int half) {
    extern __shared__ __align__(16) unsigned char dsm[];
    unsigned* keys = (unsigned*)dsm;                  // NN uints
    int* hist = (int*)(dsm + KEYS_BYTES);             // 16384 ints

    __shared__ float s_rf[32], s_rf2[32];
    __shared__ int s_ri[32], s_zi[32], s_w[32];
    __shared__ unsigned s_rmx[32], s_rmn[32];
    __shared__ int s_sel, s_want, s_idx, s_k, s_zc;
    __shared__ float s_ps, s_ls;
    __shared__ unsigned s_max, s_min;

    const int b = blockIdx.x;
    const int tid = threadIdx.x;
    const int lane = tid & 31;
    const int warp = tid >> 5;

    // hoisted: zero full hist while the LDGs below are in flight.
    #pragma unroll
    for (int q = 0; q < 4; ++q)
        ((int4*)hist)[tid + q * 1024] = make_int4(0, 0, 0, 0);

    // (1) load keys + rowstats (no atomics): max, min-of-nonzero, zero count.
    const uint4* k4 = (const uint4*)(g_keys + (size_t)b * NN);
    unsigned umax = 0u, umin = 0xFFFFFFFFu;
    int zc = 0;
    for (int i = tid; i < NU4; i += 1024) {
        uint4 v = k4[i];
        ((uint4*)keys)[i] = v;
        #define ST(x) { if (x) { umax = max(umax, (x)); umin = min(umin, (x)); } else ++zc; }
        ST(v.x) ST(v.y) ST(v.z) ST(v.w)
        #undef ST
    }
    // global positive count -> k; row pos-sum and loc-sum from tile partials.
    int c = 0;
    const uchar4* c4 = (const uchar4*)g_cnt;
    for (int i = tid; i < NT / 4; i += 1024) {
        uchar4 u = c4[i];
        c += u.x + u.y + u.z + u.w;
    }
    float ps = 0.0f, lp = 0.0f;
    for (int i = tid; i < TPR; i += 1024) {
        ps += g_psum[b * TPR + i];
        lp += g_locpart[b * TPR + i];
    }
    #pragma unroll
    for (int o = 16; o; o >>= 1) {
        c    += __shfl_xor_sync(0xFFFFFFFFu, c, o);
        zc   += __shfl_xor_sync(0xFFFFFFFFu, zc, o);
        ps   += __shfl_xor_sync(0xFFFFFFFFu, ps, o);
        lp   += __shfl_xor_sync(0xFFFFFFFFu, lp, o);
        umax  = max(umax, __shfl_xor_sync(0xFFFFFFFFu, umax, o));
        umin  = min(umin, __shfl_xor_sync(0xFFFFFFFFu, umin, o));
    }
    if (lane == 0) {
        s_ri[warp] = c; s_zi[warp] = zc; s_rf[warp] = ps; s_rf2[warp] = lp;
        s_rmx[warp] = umax; s_rmn[warp] = umin;
    }
    __syncthreads();
    if (tid == 0) {
        int tc = 0, tz = 0; float tp = 0.0f, tl = 0.0f;
        unsigned tm = 0u, tn = 0xFFFFFFFFu;
        #pragma unroll
        for (int w = 0; w < 32; ++w) {
            tc += s_ri[w]; tz += s_zi[w]; tp += s_rf[w]; tl += s_rf2[w];
            tm = max(tm, s_rmx[w]); tn = min(tn, s_rmn[w]);
        }
        int k = 3 * tc;                  // (3.0f * num_pos) -> int32, exact
        if (k > NN - 1) k = NN - 1;
        if (k < 0) k = 0;
        s_k = k; s_ps = tp; s_ls = tl; s_zc = tz; s_max = tm; s_min = tn;
    }
    __syncthreads();

    // (2) rank-k: zero group first (keys==0 sort before all nonzero, stable).
    int want = s_k;
    unsigned target = 0u;
    int r = 0;
    if (want < s_zc) {
        target = 0u; r = want;           // k-th element is a zero key
    } else {
        want -= s_zc;
        unsigned cLo = s_min, cHi = s_max;
        bool first = true;
        while (true) {
            const unsigned range = cHi - cLo;
            if (range == 0u) { target = cLo; r = want; break; }
            const int bits = 32 - __clz(range);
            const int sh = (bits > 14) ? (bits - 14) : 0;
            if (!first) {
                #pragma unroll
                for (int q = 0; q < 4; ++q)
                    ((int4*)hist)[tid + q * 1024] = make_int4(0, 0, 0, 0);
                __syncthreads();
            }
            first = false;
            for (int i = tid; i < NU4; i += 1024) {
                uint4 v = ((const uint4*)keys)[i];
                #define HB(x) if ((x) >= cLo && (x) <= cHi) atomicAdd(&hist[((x) - cLo) >> sh], 1);
                HB(v.x) HB(v.y) HB(v.z) HB(v.w)
                #undef HB
            }
            __syncthreads();
            // pick bin over 16384 bins (16/thread)
            {
                int bl[16]; int bsum = 0;
                #pragma unroll
                for (int j = 0; j < 16; ++j) { bl[j] = hist[16 * tid + j]; bsum += bl[j]; }
                int incl = bsum;
                #pragma unroll
                for (int o = 1; o < 32; o <<= 1) {
                    int t = __shfl_up_sync(0xFFFFFFFFu, incl, o);
                    if (lane >= o) incl += t;
                }
                if (lane == 31) s_w[warp] = incl;
                __syncthreads();
                if (warp == 0) {
                    int t = s_w[lane];
                    int ti = t;
                    #pragma unroll
                    for (int o = 1; o < 32; o <<= 1) {
                        int u = __shfl_up_sync(0xFFFFFFFFu, ti, o);
                        if (lane >= o) ti += u;
                    }
                    s_w[lane] = ti - t;
                }
                __syncthreads();
                const int excl = s_w[warp] + incl - bsum;
                if (want >= excl && want < excl + bsum) {
                    int w_ = want - excl;
                    #pragma unroll
                    for (int j = 0; j < 16; ++j) {
                        if (w_ < bl[j]) { s_sel = 16 * tid + j; s_want = w_; break; }
                        w_ -= bl[j];
                    }
                }
                __syncthreads();
            }
            const int B = s_sel;
            want = s_want;
            if (sh == 0) { target = cLo + (unsigned)B; r = want; break; }
            cLo += ((unsigned)B) << sh;
            {
                const unsigned span = (1u << sh) - 1u;
                unsigned nHi = cLo + span;
                if (nHi > cHi || nHi < cLo) nHi = cHi;   // clamp (incl. wrap)
                cHi = nHi;
            }
        }
    }

    // (3) resolve stable argsort index: r-th (ascending index) key == target.
    const int lo = tid * 9;                            // 9*1024 >= NN
    const int hiE = (lo + 9 < NN) ? lo + 9 : NN;
    int cnt = 0;
    for (int n = lo; n < hiE; ++n) if (keys[n] == target) ++cnt;
    int incl = cnt;
    #pragma unroll
    for (int o = 1; o < 32; o <<= 1) {
        int t = __shfl_up_sync(0xFFFFFFFFu, incl, o);
        if (lane >= o) incl += t;
    }
    if (lane == 31) s_w[warp] = incl;
    __syncthreads();
    if (warp == 0) {
        int t = s_w[lane];
        int ti = t;
        #pragma unroll
        for (int o = 1; o < 32; o <<= 1) {
            int u = __shfl_up_sync(0xFFFFFFFFu, ti, o);
            if (lane >= o) ti += u;
        }
        s_w[lane] = ti - t;
    }
    __syncthreads();
    {
        const int excl = s_w[warp] + incl - cnt;
        if (r >= excl && r < excl + cnt) {
            int rr = r - excl;
            for (int n = lo; n < hiE; ++n) {
                if (keys[n] == target) {
                    if (rr == 0) { s_idx = n; break; }
                    --rr;
                }
            }
        }
    }
    __syncthreads();
    const float thr = (float)s_idx;   // the quirk: argsort INDEX as threshold

    // (4) negsum: skipped when no key can exceed thr (exact — keys are
    // nonneg floats, uint max == float max).
    float nsum = 0.0f;
    if (__uint_as_float(s_max) > thr) {
        for (int i = tid; i < NU4; i += 1024) {
            uint4 u = ((const uint4*)keys)[i];
            float f;
            f = __uint_as_float(u.x); if (f > thr) nsum += f;
            f = __uint_as_float(u.y); if (f > thr) nsum += f;
            f = __uint_as_float(u.z); if (f > thr) nsum += f;
            f = __uint_as_float(u.w); if (f > thr) nsum += f;
        }
    }
    #pragma unroll
    for (int o = 16; o; o >>= 1) nsum += __shfl_xor_sync(0xFFFFFFFFu, nsum, o);
    if (lane == 0) s_rf[warp] = nsum;
    __syncthreads();
    if (tid == 0) {
        float t = 0.0f;
        #pragma unroll
        for (int w = 0; w < 32; ++w) t += s_rf[w];
        out[b] = s_ps + t;
        out[half + b] = s_ls;
    }
}

extern "C" void kernel_launch(void* const* d_in, const int* in_sizes, int n_in,
                              void* d_out, int out_size) {
    const int big_sz = BB * NN * CC;
    int ib[2] = {-1, -1}, is[2] = {-1, -1};
    int nb = 0, ns = 0;
    for (int i = 0; i < n_in; ++i) {
        if (in_sizes[i] == big_sz) { if (nb < 2) ib[nb] = i; ++nb; }
        else                       { if (ns < 2) is[ns] = i; ++ns; }
    }
    const float* pred_conf = (const float*)d_in[ib[0]];
    const float* gt_conf   = (const float*)d_in[ib[1]];
    const float* pred_loc  = (const float*)d_in[is[0]];
    const float* gt_loc    = (const float*)d_in[is[1]];
    float* out = (float*)d_out;
    const int half = out_size / 2;

    cudaFuncSetAttribute(select_kernel,
                         cudaFuncAttributeMaxDynamicSharedMemorySize, SEL_SMEM);

    dim3 gridc(TPR, BB);
    conf_kernel<<<gridc, 256>>>(pred_conf, gt_conf, pred_loc, gt_loc);
    select_kernel<<<BB, 1024, SEL_SMEM>>>(out, half);
}

// round 17
// speedup vs baseline: 1.4183x; 1.4183x over previous
#include <cuda_runtime.h>
#include <math.h>

#define BB 64
#define NN 8732
#define CC 81
#define TN 64                       // anchors per conf tile
#define TPR ((NN + TN - 1) / TN)    // 137 tiles per row
#define NT (BB * TPR)               // 8768 tiles
#define NU4 (NN / 4)                // 2183 uint4 per key row

#define KEYS_BYTES 34944            // NN*4 = 34928, padded to 16
#define NBINS 16384
#define SEL_SMEM (KEYS_BYTES + NBINS * 4)   // 100480 B dynamic smem

// Scratch (device globals — no runtime allocation). Every word read is written
// first in the same launch sequence: deterministic, no init kernel.
__device__ unsigned g_keys[BB * NN];     // pos -> 0, else float bits of conf_loss
__device__ unsigned char g_cnt[NT];      // per-tile positive count
__device__ float g_psum[NT];             // per-tile sum of positive conf_loss
__device__ float g_locpart[NT];          // per-tile loc loss partial

// One 64-anchor tile per 256-thread block (EXACT R14 — the proven optimum at
// 79.1us; default cache policy, plain LDG.128 staging).
// Phase 1: all 256 threads stage pred_conf tile + one-hot extraction (gt_conf
//          has exactly one nonzero per anchor -> unique writer, no atomics);
//          warps 4-5's loc float4 loads hoisted to kernel start so their
//          latency hides under the staging loop.
// Phase 2: threads 0-63 exp[0,40), 64-127 exp[40,81), 128-191 loc partial.
__global__ __launch_bounds__(256) void conf_kernel(const float* __restrict__ pc,
                                                   const float* __restrict__ gc,
                                                   const float* __restrict__ pl,
                                                   const float* __restrict__ gl) {
    __shared__ float sx[TN * CC];            // 20736 B raw pred_conf tile
    __shared__ float s_dot[TN];              // x[label] per anchor
    __shared__ unsigned char s_posb[TN];     // 1 if label != 0
    __shared__ float s_half[TN];             // Σexp classes [40,81)
    __shared__ float s_ps2[2];
    __shared__ int s_pc2[2];
    __shared__ float s_loc2[2];

    const int tid = threadIdx.x;
    const int lane = tid & 31;
    const int warp = tid >> 5;
    const int tile = blockIdx.x;
    const int b = blockIdx.y;
    const int n0 = tile * TN;
    const int nA = (n0 + TN <= NN) ? TN : (NN - n0);   // 64 or 28 (both %4==0)
    const int n4 = (nA * CC) >> 2;

    // hoisted loc loads (warps 4-5): issued before the staging loop, consumed
    // in phase 2 — latency rides under phase 1.
    float4 lA = make_float4(0.f, 0.f, 0.f, 0.f);
    float4 lG = make_float4(0.f, 0.f, 0.f, 0.f);
    if (tid >= 128 && tid < 192) {
        const int a = tid - 128;
        if (a < nA) {
            lA = ((const float4*)(pl + ((size_t)b * NN + n0) * 4))[a];
            lG = ((const float4*)(gl + ((size_t)b * NN + n0) * 4))[a];
        }
    }

    const size_t base = ((size_t)b * NN + n0) * CC;    // multiple of 4 floats
    const float4* p4 = (const float4*)(pc + base);
    const float4* g4 = (const float4*)(gc + base);
    for (int i = tid; i < n4; i += 256) {
        const float4 p = p4[i];
        ((float4*)sx)[i] = p;
        const float4 g = g4[i];
        if (g.x != 0.0f || g.y != 0.0f || g.z != 0.0f || g.w != 0.0f) {
            const float pv[4] = {p.x, p.y, p.z, p.w};
            const float gv[4] = {g.x, g.y, g.z, g.w};
            #pragma unroll
            for (int j = 0; j < 4; ++j) {
                if (gv[j] != 0.0f) {                   // gt one-hot: unique writer
                    const int f = 4 * i + j;
                    const int a = f / CC;
                    const int cls = f - a * CC;
                    s_dot[a] = pv[j] * gv[j];          // = x[label] (gt value 1.0)
                    s_posb[a] = (cls != 0) ? 1 : 0;
                }
            }
        }
    }
    __syncthreads();

    float myE = 0.0f;
    if (tid < 64) {
        // classes [0,40) for anchor tid; stride-81 rows -> conflict-free.
        if (tid < nA) {
            const float* x = sx + tid * CC;
            float e0 = 0.0f, e1 = 0.0f, e2 = 0.0f, e3 = 0.0f;
            #pragma unroll
            for (int c = 0; c < 40; c += 4) {
                e0 += __expf(x[c]);     e1 += __expf(x[c + 1]);
                e2 += __expf(x[c + 2]); e3 += __expf(x[c + 3]);
            }
            myE = (e0 + e1) + (e2 + e3);
        }
    } else if (tid < 128) {
        // classes [40,81) for anchor tid-64
        const int a = tid - 64;
        if (a < nA) {
            const float* x = sx + a * CC + 40;
            float e0 = 0.0f, e1 = 0.0f, e2 = 0.0f, e3 = 0.0f;
            #pragma unroll
            for (int c = 0; c < 40; c += 4) {
                e0 += __expf(x[c]);     e1 += __expf(x[c + 1]);
                e2 += __expf(x[c + 2]); e3 += __expf(x[c + 3]);
            }
            e0 += __expf(x[40]);                       // class 80
            s_half[a] = (e0 + e1) + (e2 + e3);
        }
    } else if (tid < 192) {
        // loc partial from the hoisted registers (no loads here).
        float ls = 0.0f;
        {
            float d, ad;
            d = lA.x - lG.x; ad = fabsf(d); if (ad > 1.0f) ls += ad - 0.5f;
            d = lA.y - lG.y; ad = fabsf(d); if (ad > 1.0f) ls += ad - 0.5f;
            d = lA.z - lG.z; ad = fabsf(d); if (ad > 1.0f) ls += ad - 0.5f;
            d = lA.w - lG.w; ad = fabsf(d); if (ad > 1.0f) ls += ad - 0.5f;
        }
        #pragma unroll
        for (int o = 16; o; o >>= 1) ls += __shfl_xor_sync(0xFFFFFFFFu, ls, o);
        if (lane == 0) s_loc2[warp - 4] = ls;
    }
    __syncthreads();

    if (tid < 64) {
        float pv = 0.0f;
        int pc_ = 0;
        if (tid < nA) {
            const float e = myE + s_half[tid];
            const float cl = __logf(e) - s_dot[tid];   // lse - x[label] > 0
            const bool pos = s_posb[tid];
            g_keys[b * NN + n0 + tid] = pos ? 0u : __float_as_uint(cl);
            if (pos) { pv = cl; pc_ = 1; }
        }
        #pragma unroll
        for (int o = 16; o; o >>= 1) {
            pv  += __shfl_xor_sync(0xFFFFFFFFu, pv, o);
            pc_ += __shfl_xor_sync(0xFFFFFFFFu, pc_, o);
        }
        if (lane == 0) { s_ps2[warp] = pv; s_pc2[warp] = pc_; }
    }
    __syncthreads();
    if (tid == 0) {
        const int t = b * TPR + tile;
        g_psum[t] = s_ps2[0] + s_ps2[1];
        g_cnt[t] = (unsigned char)(s_pc2[0] + s_pc2[1]);
        g_locpart[t] = s_loc2[0] + s_loc2[1];
    }
}

// One 1024-thread block per batch row. Adaptive-range rank-k select — EXACT
// R12/R14 state (proven 13.3us).
__global__ __launch_bounds__(1024) void select_kernel(float* __restrict__ out, int half) {
    extern __shared__ __align__(16) unsigned char dsm[];
    unsigned* keys = (unsigned*)dsm;                  // NN uints
    int* hist = (int*)(dsm + KEYS_BYTES);             // 16384 ints

    __shared__ float s_rf[32], s_rf2[32];
    __shared__ int s_ri[32], s_zi[32], s_w[32];
    __shared__ unsigned s_rmx[32], s_rmn[32];
    __shared__ int s_sel, s_want, s_idx, s_k, s_zc;
    __shared__ float s_ps, s_ls;
    __shared__ unsigned s_max, s_min;

    const int b = blockIdx.x;
    const int tid = threadIdx.x;
    const int lane = tid & 31;
    const int warp = tid >> 5;

    // hoisted: zero full hist while the LDGs below are in flight.
    #pragma unroll
    for (int q = 0; q < 4; ++q)
        ((int4*)hist)[tid + q * 1024] = make_int4(0, 0, 0, 0);

    // (1) load keys + rowstats (no atomics): max, min-of-nonzero, zero count.
    const uint4* k4 = (const uint4*)(g_keys + (size_t)b * NN);
    unsigned umax = 0u, umin = 0xFFFFFFFFu;
    int zc = 0;
    for (int i = tid; i < NU4; i += 1024) {
        uint4 v = k4[i];
        ((uint4*)keys)[i] = v;
        #define ST(x) { if (x) { umax = max(umax, (x)); umin = min(umin, (x)); } else ++zc; }
        ST(v.x) ST(v.y) ST(v.z) ST(v.w)
        #undef ST
    }
    // global positive count -> k; row pos-sum and loc-sum from tile partials.
    int c = 0;
    const uchar4* c4 = (const uchar4*)g_cnt;
    for (int i = tid; i < NT / 4; i += 1024) {
        uchar4 u = c4[i];
        c += u.x + u.y + u.z + u.w;
    }
    float ps = 0.0f, lp = 0.0f;
    for (int i = tid; i < TPR; i += 1024) {
        ps += g_psum[b * TPR + i];
        lp += g_locpart[b * TPR + i];
    }
    #pragma unroll
    for (int o = 16; o; o >>= 1) {
        c    += __shfl_xor_sync(0xFFFFFFFFu, c, o);
        zc   += __shfl_xor_sync(0xFFFFFFFFu, zc, o);
        ps   += __shfl_xor_sync(0xFFFFFFFFu, ps, o);
        lp   += __shfl_xor_sync(0xFFFFFFFFu, lp, o);
        umax  = max(umax, __shfl_xor_sync(0xFFFFFFFFu, umax, o));
        umin  = min(umin, __shfl_xor_sync(0xFFFFFFFFu, umin, o));
    }
    if (lane == 0) {
        s_ri[warp] = c; s_zi[warp] = zc; s_rf[warp] = ps; s_rf2[warp] = lp;
        s_rmx[warp] = umax; s_rmn[warp] = umin;
    }
    __syncthreads();
    if (tid == 0) {
        int tc = 0, tz = 0; float tp = 0.0f, tl = 0.0f;
        unsigned tm = 0u, tn = 0xFFFFFFFFu;
        #pragma unroll
        for (int w = 0; w < 32; ++w) {
            tc += s_ri[w]; tz += s_zi[w]; tp += s_rf[w]; tl += s_rf2[w];
            tm = max(tm, s_rmx[w]); tn = min(tn, s_rmn[w]);
        }
        int k = 3 * tc;                  // (3.0f * num_pos) -> int32, exact
        if (k > NN - 1) k = NN - 1;
        if (k < 0) k = 0;
        s_k = k; s_ps = tp; s_ls = tl; s_zc = tz; s_max = tm; s_min = tn;
    }
    __syncthreads();

    // (2) rank-k: zero group first (keys==0 sort before all nonzero, stable).
    int want = s_k;
    unsigned target = 0u;
    int r = 0;
    if (want < s_zc) {
        target = 0u; r = want;           // k-th element is a zero key
    } else {
        want -= s_zc;
        unsigned cLo = s_min, cHi = s_max;
        bool first = true;
        while (true) {
            const unsigned range = cHi - cLo;
            if (range == 0u) { target = cLo; r = want; break; }
            const int bits = 32 - __clz(range);
            const int sh = (bits > 14) ? (bits - 14) : 0;
            if (!first) {
                #pragma unroll
                for (int q = 0; q < 4; ++q)
                    ((int4*)hist)[tid + q * 1024] = make_int4(0, 0, 0, 0);
                __syncthreads();
            }
            first = false;
            for (int i = tid; i < NU4; i += 1024) {
                uint4 v = ((const uint4*)keys)[i];
                #define HB(x) if ((x) >= cLo && (x) <= cHi) atomicAdd(&hist[((x) - cLo) >> sh], 1);
                HB(v.x) HB(v.y) HB(v.z) HB(v.w)
                #undef HB
            }
            __syncthreads();
            // pick bin over 16384 bins (16/thread)
            {
                int bl[16]; int bsum = 0;
                #pragma unroll
                for (int j = 0; j < 16; ++j) { bl[j] = hist[16 * tid + j]; bsum += bl[j]; }
                int incl = bsum;
                #pragma unroll
                for (int o = 1; o < 32; o <<= 1) {
                    int t = __shfl_up_sync(0xFFFFFFFFu, incl, o);
                    if (lane >= o) incl += t;
                }
                if (lane == 31) s_w[warp] = incl;
                __syncthreads();
                if (warp == 0) {
                    int t = s_w[lane];
                    int ti = t;
                    #pragma unroll
                    for (int o = 1; o < 32; o <<= 1) {
                        int u = __shfl_up_sync(0xFFFFFFFFu, ti, o);
                        if (lane >= o) ti += u;
                    }
                    s_w[lane] = ti - t;
                }
                __syncthreads();
                const int excl = s_w[warp] + incl - bsum;
                if (want >= excl && want < excl + bsum) {
                    int w_ = want - excl;
                    #pragma unroll
                    for (int j = 0; j < 16; ++j) {
                        if (w_ < bl[j]) { s_sel = 16 * tid + j; s_want = w_; break; }
                        w_ -= bl[j];
                    }
                }
                __syncthreads();
            }
            const int B = s_sel;
            want = s_want;
            if (sh == 0) { target = cLo + (unsigned)B; r = want; break; }
            cLo += ((unsigned)B) << sh;
            {
                const unsigned span = (1u << sh) - 1u;
                unsigned nHi = cLo + span;
                if (nHi > cHi || nHi < cLo) nHi = cHi;   // clamp (incl. wrap)
                cHi = nHi;
            }
        }
    }

    // (3) resolve stable argsort index: r-th (ascending index) key == target.
    const int lo = tid * 9;                            // 9*1024 >= NN
    const int hiE = (lo + 9 < NN) ? lo + 9 : NN;
    int cnt = 0;
    for (int n = lo; n < hiE; ++n) if (keys[n] == target) ++cnt;
    int incl = cnt;
    #pragma unroll
    for (int o = 1; o < 32; o <<= 1) {
        int t = __shfl_up_sync(0xFFFFFFFFu, incl, o);
        if (lane >= o) incl += t;
    }
    if (lane == 31) s_w[warp] = incl;
    __syncthreads();
    if (warp == 0) {
        int t = s_w[lane];
        int ti = t;
        #pragma unroll
        for (int o = 1; o < 32; o <<= 1) {
            int u = __shfl_up_sync(0xFFFFFFFFu, ti, o);
            if (lane >= o) ti += u;
        }
        s_w[lane] = ti - t;
    }
    __syncthreads();
    {
        const int excl = s_w[warp] + incl - cnt;
        if (r >= excl && r < excl + cnt) {
            int rr = r - excl;
            for (int n = lo; n < hiE; ++n) {
                if (keys[n] == target) {
                    if (rr == 0) { s_idx = n; break; }
                    --rr;
                }
            }
        }
    }
    __syncthreads();
    const float thr = (float)s_idx;   // the quirk: argsort INDEX as threshold

    // (4) negsum: skipped when no key can exceed thr (exact — keys are
    // nonneg floats, uint max == float max).
    float nsum = 0.0f;
    if (__uint_as_float(s_max) > thr) {
        for (int i = tid; i < NU4; i += 1024) {
            uint4 u = ((const uint4*)keys)[i];
            float f;
            f = __uint_as_float(u.x); if (f > thr) nsum += f;
            f = __uint_as_float(u.y); if (f > thr) nsum += f;
            f = __uint_as_float(u.z); if (f > thr) nsum += f;
            f = __uint_as_float(u.w); if (f > thr) nsum += f;
        }
    }
    #pragma unroll
    for (int o = 16; o; o >>= 1) nsum += __shfl_xor_sync(0xFFFFFFFFu, nsum, o);
    if (lane == 0) s_rf[warp] = nsum;
    __syncthreads();
    if (tid == 0) {
        float t = 0.0f;
        #pragma unroll
        for (int w = 0; w < 32; ++w) t += s_rf[w];
        out[b] = s_ps + t;
        out[half + b] = s_ls;
    }
}

extern "C" void kernel_launch(void* const* d_in, const int* in_sizes, int n_in,
                              void* d_out, int out_size) {
    const int big_sz = BB * NN * CC;
    int ib[2] = {-1, -1}, is[2] = {-1, -1};
    int nb = 0, ns = 0;
    for (int i = 0; i < n_in; ++i) {
        if (in_sizes[i] == big_sz) { if (nb < 2) ib[nb] = i; ++nb; }
        else                       { if (ns < 2) is[ns] = i; ++ns; }
    }
    const float* pred_conf = (const float*)d_in[ib[0]];
    const float* gt_conf   = (const float*)d_in[ib[1]];
    const float* pred_loc  = (const float*)d_in[is[0]];
    const float* gt_loc    = (const float*)d_in[is[1]];
    float* out = (float*)d_out;
    const int half = out_size / 2;

    cudaFuncSetAttribute(select_kernel,
                         cudaFuncAttributeMaxDynamicSharedMemorySize, SEL_SMEM);

    dim3 gridc(TPR, BB);
    conf_kernel<<<gridc, 256>>>(pred_conf, gt_conf, pred_loc, gt_loc);
    select_kernel<<<BB, 1024, SEL_SMEM>>>(out, half);
}